// round 8
// baseline (speedup 1.0000x reference)
#include <cuda_runtime.h>
#include <cooperative_groups.h>

namespace cg = cooperative_groups;

// Problem constants (fixed by the reference)
#define BATCH 128
#define TSTEPS 2048
#define INDIM 32
#define HDIM 256
#define LDIM 16

#define CLS 8          // cluster size = CTAs per batch-group
#define TB 256         // threads per CTA (8 warps)

struct Smem {
    float hbuf[2][8][8][32];        // [buf][src rank][batch][lane]   16KB
    float4 scratch[2][8][8][32];    // [parity][kchunk][batch][col]   64KB
    float xbuf[2][8][32];           // [parity][batch][xdim]           2KB
    unsigned long long mbars[2];
};
#define SMEM_BYTES ((int)sizeof(Smem))

__device__ __forceinline__ unsigned long long pk2(float lo, float hi) {
    return ((unsigned long long)__float_as_uint(hi) << 32) |
           (unsigned long long)__float_as_uint(lo);
}
__device__ __forceinline__ float sum2(unsigned long long v) {
    return __uint_as_float((unsigned int)v) +
           __uint_as_float((unsigned int)(v >> 32));
}
#define FMA2(acc, w, h) \
    asm("fma.rn.f32x2 %0, %1, %2, %0;" : "+l"(acc) : "l"(w), "l"(h))

__device__ __forceinline__ unsigned smem_u32(const void* p) {
    unsigned r;
    asm("{ .reg .u64 t; cvta.to.shared.u64 t, %1; cvt.u32.u64 %0, t; }"
        : "=r"(r) : "l"(p));
    return r;
}

__device__ __forceinline__ float fast_sigmoid(float x) {
    return __fdividef(1.0f, 1.0f + __expf(-x));
}
__device__ __forceinline__ float fast_tanh(float x) {
    float ex = __expf(2.0f * x);
    return fmaf(-2.0f, __fdividef(1.0f, ex + 1.0f), 1.0f);
}

__device__ __forceinline__ void mbar_wait(unsigned addr, unsigned parity) {
    asm volatile(
        "{\n\t"
        ".reg .pred P;\n\t"
        "WL_%=:\n\t"
        "mbarrier.try_wait.parity.acquire.cta.shared::cta.b64 P, [%0], %1, 0x989680;\n\t"
        "@P bra.uni WD_%=;\n\t"
        "bra.uni WL_%=;\n\t"
        "WD_%=:\n\t"
        "}"
        :: "r"(addr), "r"(parity) : "memory");
}

__global__ void __cluster_dims__(CLS, 1, 1) __launch_bounds__(TB, 1)
gru_persistent_kernel(const float* __restrict__ xg,      // [B,T,IN]
                      const float* __restrict__ xl,      // [B,T,L]
                      const float* __restrict__ h0,      // [B,H]
                      const float* __restrict__ Wih,     // [3H,IN]
                      const float* __restrict__ Whh,     // [3H,H]
                      const float* __restrict__ bias,    // [3H]
                      const float* __restrict__ bias_n,  // [H]
                      float* __restrict__ out)           // [B,T,1]
{
    extern __shared__ __align__(16) char dynsmem[];
    Smem& sm = *reinterpret_cast<Smem*>(dynsmem);

    cg::cluster_group cluster = cg::this_cluster();
    const int rank = (int)cluster.block_rank();     // owns cols [32r, 32r+32)
    const int cid  = blockIdx.x / CLS;              // owns batches [8c, 8c+8)
    const int B0   = cid * 8;
    const int tid  = threadIdx.x;
    const int lane = tid & 31;
    const int warp = tid >> 5;      // FMA phase: k-chunk (= src rank); gate phase: batch
    const int col  = rank * 32 + lane;

    // ---- Weights in registers, packed (even k, odd k) ----
    unsigned long long wd[3][16];   // Whh[g][col][warp*32 .. warp*32+31]
    unsigned long long wi[3][2];    // Wih[g][col][warp*4 .. warp*4+3]
#pragma unroll
    for (int g = 0; g < 3; g++) {
        const float* wr = Whh + (size_t)(g * HDIM + col) * HDIM + warp * 32;
#pragma unroll
        for (int p = 0; p < 16; p++) wd[g][p] = pk2(wr[2 * p], wr[2 * p + 1]);
        const float* wx = Wih + (size_t)(g * HDIM + col) * INDIM + warp * 4;
        wi[g][0] = pk2(wx[0], wx[1]);
        wi[g][1] = pk2(wx[2], wx[3]);
    }
    const float b_r  = bias[col];
    const float b_z  = bias[HDIM + col];
    const float b_ni = bias[2 * HDIM + col];
    const float b_n2 = bias_n[col];

    const unsigned mloc = smem_u32(&sm.mbars[0]);
    const unsigned hloc = smem_u32(&sm.hbuf[0][0][0][0]);
    if (tid == 0) {
        asm volatile("mbarrier.init.shared.b64 [%0], 1;" :: "r"(mloc)     : "memory");
        asm volatile("mbarrier.init.shared.b64 [%0], 1;" :: "r"(mloc + 8) : "memory");
    }

    // ---- Init: buffer 0 holds full h0, laid out [src][batch][lane] ----
    for (int idx = tid; idx < 8 * HDIM; idx += TB) {
        int src = idx >> 8, b = (idx >> 5) & 7, l = idx & 31;
        sm.hbuf[0][src][b][l] = h0[(size_t)(B0 + b) * HDIM + src * 32 + l];
    }
    sm.xbuf[0][warp][lane] = xg[(size_t)(B0 + warp) * TSTEPS * INDIM + lane];

    float hreg = h0[(size_t)(B0 + warp) * HDIM + col];   // h_prev (batch=warp, col)
    float xl_reg = 0.f;
    if (rank == 0 && lane < LDIM)
        xl_reg = xl[(size_t)(B0 + warp) * TSTEPS * LDIM + lane];

    __syncthreads();
    cluster.sync();    // peers' mbarriers initialized before any bulk copy lands

    if (tid == 0) {
        // complete mbar[0] phase 0 (buffer 0 pre-filled locally)
        asm volatile("mbarrier.arrive.shared.b64 _, [%0];" :: "r"(mloc) : "memory");
        // arm mbar[1] for step 1: 8 sources x 8 warps x 128B
        asm volatile("mbarrier.arrive.expect_tx.shared.b64 _, [%0], %1;"
                     :: "r"(mloc + 8), "r"(8192u) : "memory");
    }

    // Per-thread send target (lane 0..7 -> rank 'lane', incl. self)
    unsigned my_pb = 0, my_pm = 0;
    {
        int tgt = lane & 7;
        asm("mapa.shared::cluster.u32 %0, %1, %2;" : "=r"(my_pb) : "r"(hloc), "r"(tgt));
        asm("mapa.shared::cluster.u32 %0, %1, %2;" : "=r"(my_pm) : "r"(mloc), "r"(tgt));
    }

    for (int t = 0; t < TSTEPS; t++) {
        const int buf = t & 1;
        const unsigned par = (unsigned)((t >> 1) & 1);

        mbar_wait(mloc + (unsigned)(buf * 8), par);   // full h (incl. own) local

        // Re-arm this buffer's mbar for step t+2 (pre-S1 => ordered before any
        // send that can target it, transitively through the peer handshake)
        if (tid == 0 && t + 2 < TSTEPS) {
            asm volatile("mbarrier.arrive.expect_tx.shared.b64 _, [%0], %1;"
                         :: "r"(mloc + (unsigned)(buf * 8)), "r"(8192u) : "memory");
        }

        const int tn = (t + 1 < TSTEPS) ? t + 1 : t;
        float xnext = xg[(size_t)(B0 + warp) * TSTEPS * INDIM +
                         (size_t)tn * INDIM + lane];

        // ---- Matvec partials: thread = (col=lane, kchunk=warp) ----
        // 2 groups of 4 batches: early STS, fewer live accumulators
#pragma unroll
        for (int bg = 0; bg < 2; bg++) {
            unsigned long long aR[4], aZ[4], aNh[4], aNi[4];
#pragma unroll
            for (int j = 0; j < 4; j++) { aR[j] = 0ull; aZ[j] = 0ull; aNh[j] = 0ull; aNi[j] = 0ull; }

#pragma unroll
            for (int j = 0; j < 4; j++) {
                const int b = bg * 4 + j;
                ulonglong2 x2 = *reinterpret_cast<const ulonglong2*>(
                    &sm.xbuf[buf][b][warp * 4]);
                FMA2(aR[j],  wi[0][0], x2.x); FMA2(aR[j],  wi[0][1], x2.y);
                FMA2(aZ[j],  wi[1][0], x2.x); FMA2(aZ[j],  wi[1][1], x2.y);
                FMA2(aNi[j], wi[2][0], x2.x); FMA2(aNi[j], wi[2][1], x2.y);
            }

#pragma unroll
            for (int i = 0; i < 8; i++) {
#pragma unroll
                for (int j = 0; j < 4; j++) {
                    const int b = bg * 4 + j;
                    // broadcast load: all lanes read the same 16B
                    ulonglong2 h2 = *reinterpret_cast<const ulonglong2*>(
                        &sm.hbuf[buf][warp][b][4 * i]);
                    FMA2(aR[j],  wd[0][2 * i],     h2.x);
                    FMA2(aR[j],  wd[0][2 * i + 1], h2.y);
                    FMA2(aZ[j],  wd[1][2 * i],     h2.x);
                    FMA2(aZ[j],  wd[1][2 * i + 1], h2.y);
                    FMA2(aNh[j], wd[2][2 * i],     h2.x);
                    FMA2(aNh[j], wd[2][2 * i + 1], h2.y);
                }
            }

#pragma unroll
            for (int j = 0; j < 4; j++) {
                sm.scratch[buf][warp][bg * 4 + j][lane] =
                    make_float4(sum2(aR[j]), sum2(aZ[j]), sum2(aNh[j]), sum2(aNi[j]));
            }
        }

        // stash next x BEFORE the barrier (parity buffer; readers are post-S1)
        sm.xbuf[buf ^ 1][warp][lane] = xnext;

        __syncthreads();   // S1: partials + xbuf visible; hbuf reads of step t done

        // ---- Reduce + gates: thread = (batch=warp, col=lane) ----
        float sR = 0.f, sZ = 0.f, sNh = 0.f, sNi = 0.f;
#pragma unroll
        for (int kc = 0; kc < 8; kc++) {
            float4 v = sm.scratch[buf][kc][warp][lane];
            sR += v.x; sZ += v.y; sNh += v.z; sNi += v.w;
        }
        const float r = fast_sigmoid(sR + b_r);
        const float z = fast_sigmoid(sZ + b_z);
        const float n = fast_tanh(sNi + b_ni + r * (sNh + b_n2));
        hreg = n + z * (hreg - n);

        // ---- Eager per-warp exchange: stage 128B row, send to all 8 ranks ----
        if (t + 1 < TSTEPS) {
            sm.hbuf[buf ^ 1][rank][warp][lane] = hreg;   // my batch-row, own cols
            __syncwarp();
            asm volatile("fence.proxy.async.shared::cta;" ::: "memory");
            if (lane < 8) {
                const unsigned off = (unsigned)((buf ^ 1) * 8192 + rank * 1024 + warp * 128);
                asm volatile(
                    "cp.async.bulk.shared::cluster.shared::cta.mbarrier::complete_tx::bytes "
                    "[%0], [%1], %2, [%3];"
                    :: "r"(my_pb + off), "r"(hloc + off), "r"(128u),
                       "r"(my_pm + (unsigned)((buf ^ 1) * 8)) : "memory");
            }
        }

        // ---- Readout (columns 0..15 live in rank 0) ----
        if (rank == 0) {
            float prod = (lane < LDIM) ? hreg * xl_reg : 0.f;
#pragma unroll
            for (int off = 16; off; off >>= 1)
                prod += __shfl_xor_sync(0xffffffffu, prod, off);
            if (lane == 0) out[(size_t)(B0 + warp) * TSTEPS + t] = prod;
            if (lane < LDIM)
                xl_reg = xl[(size_t)(B0 + warp) * TSTEPS * LDIM +
                            (size_t)tn * LDIM + lane];
        }
    }

    cluster.sync();   // clean distributed exit
}

extern "C" void kernel_launch(void* const* d_in, const int* in_sizes, int n_in,
                              void* d_out, int out_size) {
    (void)in_sizes; (void)n_in; (void)out_size;
    const float* xg     = (const float*)d_in[0];  // input_gru   [128,2048,32]
    const float* xl     = (const float*)d_in[1];  // input_linear[128,2048,16]
    const float* h0     = (const float*)d_in[2];  // init_hidden [128,256]
    const float* Wih    = (const float*)d_in[3];  // [768,32]
    const float* Whh    = (const float*)d_in[4];  // [768,256]
    const float* bias   = (const float*)d_in[5];  // [768]
    const float* bias_n = (const float*)d_in[6];  // [256]
    float* out = (float*)d_out;                   // [128,2048,1]

    cudaFuncSetAttribute(gru_persistent_kernel,
                         cudaFuncAttributeMaxDynamicSharedMemorySize, SMEM_BYTES);

    gru_persistent_kernel<<<dim3(BATCH), dim3(TB), SMEM_BYTES>>>(
        xg, xl, h0, Wih, Whh, bias, bias_n, out);
}